// round 1
// baseline (speedup 1.0000x reference)
#include <cuda_runtime.h>
#include <cuda_bf16.h>
#include <cstdint>

// Problem constants
#define B_ 8
#define S_ 1024
#define E_ 1024
#define H_ 16
#define D_ 64
#define ROWS (B_ * S_)          // 8192
#define GROUPS (B_ * H_)        // 128
#define GCHUNK (S_ * D_)        // 65536 floats per (b,h) group

// Scratch (device globals; allocation is forbidden)
__device__ float g_q[ROWS * E_];
__device__ float g_k[ROWS * E_];
__device__ float g_v[ROWS * E_];
__device__ float g_att[ROWS * E_];

// ---------------------------------------------------------------------------
// SGEMM: C[M,N] = A[M,K] @ B[K,N] (+ bias). M,N,K divisible by tile sizes.
// BM=BN=128, BK=8, TM=TN=8, 256 threads.
// ---------------------------------------------------------------------------
#define BM 128
#define BN 128
#define BK 8
#define TM 8
#define TN 8

__global__ __launch_bounds__(256) void sgemm_bias(
    const float* __restrict__ A, const float* __restrict__ Bmat,
    const float* __restrict__ bias, float* __restrict__ C,
    int M, int N, int K)
{
    __shared__ float As[BK][BM];
    __shared__ float Bs[BK][BN];

    const int tid = threadIdx.x;
    const int bx = blockIdx.x;   // N tile
    const int by = blockIdx.y;   // M tile

    const float* Ablk = A + (size_t)by * BM * K;
    const float* Bblk = Bmat + (size_t)bx * BN;

    // A loader: 128x8 tile, 256 threads x float4
    const int aRow  = tid >> 1;          // 0..127
    const int aCol4 = (tid & 1) * 4;     // 0 or 4
    // B loader: 8x128 tile
    const int bRow  = tid >> 5;          // 0..7
    const int bCol4 = (tid & 31) * 4;    // 0..124

    const int tr = (tid >> 4) * TM;      // 0..120
    const int tc = (tid & 15) * TN;      // 0..120

    float acc[TM][TN];
    #pragma unroll
    for (int i = 0; i < TM; i++)
        #pragma unroll
        for (int j = 0; j < TN; j++) acc[i][j] = 0.0f;

    float ra[TM], rb[TN];

    for (int k0 = 0; k0 < K; k0 += BK) {
        float4 av = *(const float4*)(Ablk + (size_t)aRow * K + k0 + aCol4);
        As[aCol4 + 0][aRow] = av.x;
        As[aCol4 + 1][aRow] = av.y;
        As[aCol4 + 2][aRow] = av.z;
        As[aCol4 + 3][aRow] = av.w;
        float4 bv = *(const float4*)(Bblk + (size_t)(k0 + bRow) * N + bCol4);
        *(float4*)&Bs[bRow][bCol4] = bv;
        __syncthreads();

        #pragma unroll
        for (int k = 0; k < BK; k++) {
            #pragma unroll
            for (int i = 0; i < TM; i += 4)
                *(float4*)&ra[i] = *(float4*)&As[k][tr + i];
            #pragma unroll
            for (int j = 0; j < TN; j += 4)
                *(float4*)&rb[j] = *(float4*)&Bs[k][tc + j];
            #pragma unroll
            for (int i = 0; i < TM; i++)
                #pragma unroll
                for (int j = 0; j < TN; j++)
                    acc[i][j] += ra[i] * rb[j];
        }
        __syncthreads();
    }

    // Epilogue
    float bv[TN];
    if (bias != nullptr) {
        #pragma unroll
        for (int j = 0; j < TN; j += 4)
            *(float4*)&bv[j] = *(const float4*)&bias[(size_t)bx * BN + tc + j];
    } else {
        #pragma unroll
        for (int j = 0; j < TN; j++) bv[j] = 0.0f;
    }
    #pragma unroll
    for (int i = 0; i < TM; i++) {
        float* crow = C + (size_t)(by * BM + tr + i) * N + bx * BN + tc;
        #pragma unroll
        for (int j = 0; j < TN; j += 4) {
            float4 v;
            v.x = acc[i][j + 0] + bv[j + 0];
            v.y = acc[i][j + 1] + bv[j + 1];
            v.z = acc[i][j + 2] + bv[j + 2];
            v.w = acc[i][j + 3] + bv[j + 3];
            *(float4*)(crow + j) = v;
        }
    }
}

// ---------------------------------------------------------------------------
// Flash attention over 128 groups of [1024,64]. One block = 128 query rows of
// one group; one thread = one query row (q and O live in registers; K/V chunk
// reads are warp-uniform smem broadcasts).
// grid = (S/128, GROUPS), block = 128
// ---------------------------------------------------------------------------
#define BC 32   // key chunk

__global__ __launch_bounds__(128) void attn_kernel()
{
    const int g   = blockIdx.y;            // 0..127  (b*16 + h)
    const int r0  = blockIdx.x * 128;      // query row base
    const int tid = threadIdx.x;
    const int row = r0 + tid;              // s2 index

    const float* Qp = g_q + (size_t)g * GCHUNK;
    const float* Kp = g_k + (size_t)g * GCHUNK;
    const float* Vp = g_v + (size_t)g * GCHUNK;

    __shared__ float Ks[BC][D_];
    __shared__ float Vs[BC][D_];

    float q[D_], O[D_];
    #pragma unroll
    for (int d = 0; d < D_; d += 4)
        *(float4*)&q[d] = *(const float4*)&Qp[(size_t)row * D_ + d];
    #pragma unroll
    for (int d = 0; d < D_; d++) O[d] = 0.0f;

    float m = -1e30f, l = 0.0f;
    const float scale = 0.03125f;          // E^-0.5 = 1/32

    for (int c0 = 0; c0 < S_; c0 += BC) {
        __syncthreads();
        // stage K/V chunk: BC*D_ = 2048 floats each; 128 thr x 4 float4
        #pragma unroll
        for (int it = 0; it < 4; it++) {
            int idx = tid + it * 128;          // 0..511 float4 slots
            int jj = idx >> 4;
            int dd = (idx & 15) * 4;
            *(float4*)&Ks[jj][dd] = *(const float4*)&Kp[(size_t)(c0 + jj) * D_ + dd];
            *(float4*)&Vs[jj][dd] = *(const float4*)&Vp[(size_t)(c0 + jj) * D_ + dd];
        }
        __syncthreads();

        // s[j] = q . K_j  (d-outer / j-inner: 32 independent FMA chains)
        float s[BC];
        #pragma unroll
        for (int j = 0; j < BC; j++) s[j] = 0.0f;
        #pragma unroll
        for (int d = 0; d < D_; d += 4) {
            const float q0 = q[d], q1 = q[d + 1], q2 = q[d + 2], q3 = q[d + 3];
            #pragma unroll
            for (int j = 0; j < BC; j++) {
                float4 kv = *(float4*)&Ks[j][d];
                s[j] += q0 * kv.x + q1 * kv.y + q2 * kv.z + q3 * kv.w;
            }
        }

        // online softmax update
        float mc = m;
        #pragma unroll
        for (int j = 0; j < BC; j++) { s[j] *= scale; mc = fmaxf(mc, s[j]); }
        const float alpha = __expf(m - mc);
        m = mc;
        float lsum = 0.0f;
        #pragma unroll
        for (int j = 0; j < BC; j++) { s[j] = __expf(s[j] - mc); lsum += s[j]; }
        l = l * alpha + lsum;

        #pragma unroll
        for (int d = 0; d < D_; d++) O[d] *= alpha;

        // O += P @ V_chunk
        #pragma unroll
        for (int j = 0; j < BC; j++) {
            const float pj = s[j];
            #pragma unroll
            for (int d = 0; d < D_; d += 4) {
                float4 vv = *(float4*)&Vs[j][d];
                O[d + 0] += pj * vv.x;
                O[d + 1] += pj * vv.y;
                O[d + 2] += pj * vv.z;
                O[d + 3] += pj * vv.w;
            }
        }
    }

    // write to [B,S,H,D] layout for the output projection
    const float inv = 1.0f / l;
    const int b = g >> 4, h = g & 15;
    float* outp = g_att + ((size_t)(b * S_ + row)) * E_ + h * D_;
    #pragma unroll
    for (int d = 0; d < D_; d += 4) {
        float4 v;
        v.x = O[d + 0] * inv;
        v.y = O[d + 1] * inv;
        v.z = O[d + 2] * inv;
        v.w = O[d + 3] * inv;
        *(float4*)&outp[d] = v;
    }
}

// ---------------------------------------------------------------------------
extern "C" void kernel_launch(void* const* d_in, const int* in_sizes, int n_in,
                              void* d_out, int out_size)
{
    const float* hs    = (const float*)d_in[0];
    const float* w_q   = (const float*)d_in[1];
    const float* w_k   = (const float*)d_in[2];
    const float* w_v   = (const float*)d_in[3];
    const float* w_out = (const float*)d_in[4];
    const float* b_out = (const float*)d_in[5];
    float* out = (float*)d_out;

    float *qp, *kp, *vp, *ap;
    cudaGetSymbolAddress((void**)&qp, g_q);
    cudaGetSymbolAddress((void**)&kp, g_k);
    cudaGetSymbolAddress((void**)&vp, g_v);
    cudaGetSymbolAddress((void**)&ap, g_att);

    dim3 gemmGrid(E_ / BN, ROWS / BM);   // (8, 64)
    sgemm_bias<<<gemmGrid, 256>>>(hs, w_q, nullptr, qp, ROWS, E_, E_);
    sgemm_bias<<<gemmGrid, 256>>>(hs, w_k, nullptr, kp, ROWS, E_, E_);
    sgemm_bias<<<gemmGrid, 256>>>(hs, w_v, nullptr, vp, ROWS, E_, E_);

    dim3 attnGrid(S_ / 128, GROUPS);     // (8, 128)
    attn_kernel<<<attnGrid, 128>>>();

    sgemm_bias<<<gemmGrid, 256>>>(ap, w_out, b_out, out, ROWS, E_, E_);
}

// round 3
// speedup vs baseline: 1.4596x; 1.4596x over previous
#include <cuda_runtime.h>
#include <cuda_bf16.h>
#include <cstdint>

// Problem constants
#define B_ 8
#define S_ 1024
#define E_ 1024
#define H_ 16
#define D_ 64
#define ROWS (B_ * S_)          // 8192
#define GROUPS (B_ * H_)        // 128
#define GCHUNK (S_ * D_)        // 65536 floats per (b,h) group

// Scratch (device globals; allocation is forbidden)
__device__ float g_q[ROWS * E_];
__device__ float g_k[ROWS * E_];
__device__ float g_v[ROWS * E_];
__device__ float g_att[ROWS * E_];

// ---------------------------------------------------------------------------
// TF32 tensor-core GEMM: C[M,N] = A[M,K] @ B[K,N] (+ bias)
// BM=BN=128, BK=16, 256 threads = 8 warps (2 x 4), warp tile 64x32.
// mma.sync.aligned.m16n8k8.row.col.f32.tf32.tf32.f32
// ---------------------------------------------------------------------------
#define BM 128
#define BN 128
#define BK 16
#define SMP 132    // padded smem row stride (conflict-free fragment gathers)

__device__ __forceinline__ uint32_t f2tf(float x) {
    uint32_t u;
    asm("cvt.rna.tf32.f32 %0, %1;" : "=r"(u) : "f"(x));
    return u;
}

__device__ __forceinline__ void mma_tf32(float c[4], uint32_t a0, uint32_t a1,
                                         uint32_t a2, uint32_t a3,
                                         uint32_t b0, uint32_t b1) {
    asm volatile(
        "mma.sync.aligned.m16n8k8.row.col.f32.tf32.tf32.f32 "
        "{%0,%1,%2,%3},{%4,%5,%6,%7},{%8,%9},{%0,%1,%2,%3};"
        : "+f"(c[0]), "+f"(c[1]), "+f"(c[2]), "+f"(c[3])
        : "r"(a0), "r"(a1), "r"(a2), "r"(a3), "r"(b0), "r"(b1));
}

__global__ __launch_bounds__(256) void sgemm_tf32(
    const float* __restrict__ A, const float* __restrict__ Bmat,
    const float* __restrict__ bias, float* __restrict__ C,
    int M, int N, int K)
{
    __shared__ uint32_t As[BK][SMP];   // [k][m], tf32 bits
    __shared__ uint32_t Bs[BK][SMP];   // [k][n], tf32 bits

    const int tid  = threadIdx.x;
    const int lane = tid & 31;
    const int wid  = tid >> 5;
    const int wm   = wid >> 2;          // 0..1  (64-row slab)
    const int wn   = wid & 3;           // 0..3  (32-col slab)
    const int gid  = lane >> 2;         // 0..7
    const int tig  = lane & 3;          // 0..3

    const int bx = blockIdx.x;          // N tile
    const int by = blockIdx.y;          // M tile

    const float* Ablk = A + (size_t)by * BM * K;
    const float* Bblk = Bmat + (size_t)bx * BN;

    // A loader: 128 rows x 16 k. thread t -> row t>>1, k-cols (t&1)*8 .. +7
    const int ar = tid >> 1;
    const int ac = (tid & 1) * 8;
    // B loader: 16 rows x 128 cols. thread t -> rows t>>5 and (t>>5)+8, cols (t&31)*4
    const int br = tid >> 5;
    const int bc = (tid & 31) * 4;

    float acc[4][4][4];
    #pragma unroll
    for (int i = 0; i < 4; i++)
        #pragma unroll
        for (int j = 0; j < 4; j++)
            #pragma unroll
            for (int f = 0; f < 4; f++) acc[i][j][f] = 0.0f;

    // prefetch tile 0
    float4 pa0, pa1, pb0, pb1;
    pa0 = *(const float4*)(Ablk + (size_t)ar * K + ac);
    pa1 = *(const float4*)(Ablk + (size_t)ar * K + ac + 4);
    pb0 = *(const float4*)(Bblk + (size_t)br * N + bc);
    pb1 = *(const float4*)(Bblk + (size_t)(br + 8) * N + bc);

    for (int k0 = 0; k0 < K; k0 += BK) {
        // commit prefetched tile to smem (converted to tf32)
        As[ac + 0][ar] = f2tf(pa0.x);
        As[ac + 1][ar] = f2tf(pa0.y);
        As[ac + 2][ar] = f2tf(pa0.z);
        As[ac + 3][ar] = f2tf(pa0.w);
        As[ac + 4][ar] = f2tf(pa1.x);
        As[ac + 5][ar] = f2tf(pa1.y);
        As[ac + 6][ar] = f2tf(pa1.z);
        As[ac + 7][ar] = f2tf(pa1.w);
        Bs[br][bc + 0] = f2tf(pb0.x);
        Bs[br][bc + 1] = f2tf(pb0.y);
        Bs[br][bc + 2] = f2tf(pb0.z);
        Bs[br][bc + 3] = f2tf(pb0.w);
        Bs[br + 8][bc + 0] = f2tf(pb1.x);
        Bs[br + 8][bc + 1] = f2tf(pb1.y);
        Bs[br + 8][bc + 2] = f2tf(pb1.z);
        Bs[br + 8][bc + 3] = f2tf(pb1.w);
        __syncthreads();

        // prefetch next tile
        if (k0 + BK < K) {
            const float* An = Ablk + k0 + BK;
            const float* Bn = Bblk + (size_t)(k0 + BK) * N;
            pa0 = *(const float4*)(An + (size_t)ar * K + ac);
            pa1 = *(const float4*)(An + (size_t)ar * K + ac + 4);
            pb0 = *(const float4*)(Bn + (size_t)br * N + bc);
            pb1 = *(const float4*)(Bn + (size_t)(br + 8) * N + bc);
        }

        // compute: 2 k-steps of 8
        #pragma unroll
        for (int s = 0; s < 2; s++) {
            const int kb = s * 8;
            uint32_t af[4][4], bf[4][2];
            #pragma unroll
            for (int i = 0; i < 4; i++) {
                const int rb = wm * 64 + i * 16;
                af[i][0] = As[kb + tig][rb + gid];
                af[i][1] = As[kb + tig][rb + 8 + gid];
                af[i][2] = As[kb + 4 + tig][rb + gid];
                af[i][3] = As[kb + 4 + tig][rb + 8 + gid];
            }
            #pragma unroll
            for (int j = 0; j < 4; j++) {
                const int cb = wn * 32 + j * 8;
                bf[j][0] = Bs[kb + tig][cb + gid];
                bf[j][1] = Bs[kb + 4 + tig][cb + gid];
            }
            #pragma unroll
            for (int i = 0; i < 4; i++)
                #pragma unroll
                for (int j = 0; j < 4; j++)
                    mma_tf32(acc[i][j], af[i][0], af[i][1], af[i][2], af[i][3],
                             bf[j][0], bf[j][1]);
        }
        __syncthreads();
    }

    // Epilogue: C fragment layout — c0,c1 at row gid, cols 2*tig,2*tig+1; c2,c3 at row gid+8
    #pragma unroll
    for (int i = 0; i < 4; i++) {
        const int row0 = by * BM + wm * 64 + i * 16 + gid;
        #pragma unroll
        for (int j = 0; j < 4; j++) {
            const int col = bx * BN + wn * 32 + j * 8 + 2 * tig;
            float b0 = 0.0f, b1 = 0.0f;
            if (bias != nullptr) { b0 = bias[col]; b1 = bias[col + 1]; }
            float2 v0 = make_float2(acc[i][j][0] + b0, acc[i][j][1] + b1);
            float2 v1 = make_float2(acc[i][j][2] + b0, acc[i][j][3] + b1);
            *(float2*)(C + (size_t)row0 * N + col) = v0;
            *(float2*)(C + (size_t)(row0 + 8) * N + col) = v1;
        }
    }
}

// ---------------------------------------------------------------------------
// Flash attention over 128 groups of [1024,64]. One block = 128 query rows of
// one group; one thread = one query row.
// grid = (S/128, GROUPS), block = 128
// ---------------------------------------------------------------------------
#define BC 32   // key chunk

__global__ __launch_bounds__(128) void attn_kernel()
{
    const int g   = blockIdx.y;            // 0..127  (b*16 + h)
    const int r0  = blockIdx.x * 128;      // query row base
    const int tid = threadIdx.x;
    const int row = r0 + tid;              // s2 index

    const float* Qp = g_q + (size_t)g * GCHUNK;
    const float* Kp = g_k + (size_t)g * GCHUNK;
    const float* Vp = g_v + (size_t)g * GCHUNK;

    __shared__ float Ks[BC][D_];
    __shared__ float Vs[BC][D_];

    float q[D_], O[D_];
    #pragma unroll
    for (int d = 0; d < D_; d += 4)
        *(float4*)&q[d] = *(const float4*)&Qp[(size_t)row * D_ + d];
    #pragma unroll
    for (int d = 0; d < D_; d++) O[d] = 0.0f;

    float m = -1e30f, l = 0.0f;
    const float scale = 0.03125f;          // E^-0.5 = 1/32

    for (int c0 = 0; c0 < S_; c0 += BC) {
        __syncthreads();
        #pragma unroll
        for (int it = 0; it < 4; it++) {
            int idx = tid + it * 128;          // 0..511 float4 slots
            int jj = idx >> 4;
            int dd = (idx & 15) * 4;
            *(float4*)&Ks[jj][dd] = *(const float4*)&Kp[(size_t)(c0 + jj) * D_ + dd];
            *(float4*)&Vs[jj][dd] = *(const float4*)&Vp[(size_t)(c0 + jj) * D_ + dd];
        }
        __syncthreads();

        float s[BC];
        #pragma unroll
        for (int j = 0; j < BC; j++) s[j] = 0.0f;
        #pragma unroll
        for (int d = 0; d < D_; d += 4) {
            const float q0 = q[d], q1 = q[d + 1], q2 = q[d + 2], q3 = q[d + 3];
            #pragma unroll
            for (int j = 0; j < BC; j++) {
                float4 kv = *(float4*)&Ks[j][d];
                s[j] += q0 * kv.x + q1 * kv.y + q2 * kv.z + q3 * kv.w;
            }
        }

        float mc = m;
        #pragma unroll
        for (int j = 0; j < BC; j++) { s[j] *= scale; mc = fmaxf(mc, s[j]); }
        const float alpha = __expf(m - mc);
        m = mc;
        float lsum = 0.0f;
        #pragma unroll
        for (int j = 0; j < BC; j++) { s[j] = __expf(s[j] - mc); lsum += s[j]; }
        l = l * alpha + lsum;

        #pragma unroll
        for (int d = 0; d < D_; d++) O[d] *= alpha;

        #pragma unroll
        for (int j = 0; j < BC; j++) {
            const float pj = s[j];
            #pragma unroll
            for (int d = 0; d < D_; d += 4) {
                float4 vv = *(float4*)&Vs[j][d];
                O[d + 0] += pj * vv.x;
                O[d + 1] += pj * vv.y;
                O[d + 2] += pj * vv.z;
                O[d + 3] += pj * vv.w;
            }
        }
    }

    const float inv = 1.0f / l;
    const int b = g >> 4, h = g & 15;
    float* outp = g_att + ((size_t)(b * S_ + row)) * E_ + h * D_;
    #pragma unroll
    for (int d = 0; d < D_; d += 4) {
        float4 v;
        v.x = O[d + 0] * inv;
        v.y = O[d + 1] * inv;
        v.z = O[d + 2] * inv;
        v.w = O[d + 3] * inv;
        *(float4*)&outp[d] = v;
    }
}

// ---------------------------------------------------------------------------
extern "C" void kernel_launch(void* const* d_in, const int* in_sizes, int n_in,
                              void* d_out, int out_size)
{
    const float* hs    = (const float*)d_in[0];
    const float* w_q   = (const float*)d_in[1];
    const float* w_k   = (const float*)d_in[2];
    const float* w_v   = (const float*)d_in[3];
    const float* w_out = (const float*)d_in[4];
    const float* b_out = (const float*)d_in[5];
    float* out = (float*)d_out;

    float *qp, *kp, *vp, *ap;
    cudaGetSymbolAddress((void**)&qp, g_q);
    cudaGetSymbolAddress((void**)&kp, g_k);
    cudaGetSymbolAddress((void**)&vp, g_v);
    cudaGetSymbolAddress((void**)&ap, g_att);

    dim3 gemmGrid(E_ / BN, ROWS / BM);   // (8, 64)
    sgemm_tf32<<<gemmGrid, 256>>>(hs, w_q, nullptr, qp, ROWS, E_, E_);
    sgemm_tf32<<<gemmGrid, 256>>>(hs, w_k, nullptr, kp, ROWS, E_, E_);
    sgemm_tf32<<<gemmGrid, 256>>>(hs, w_v, nullptr, vp, ROWS, E_, E_);

    dim3 attnGrid(S_ / 128, GROUPS);     // (8, 128)
    attn_kernel<<<attnGrid, 128>>>();

    sgemm_tf32<<<gemmGrid, 256>>>(ap, w_out, b_out, out, ROWS, E_, E_);
}

// round 4
// speedup vs baseline: 2.5714x; 1.7617x over previous
#include <cuda_runtime.h>
#include <cuda_bf16.h>
#include <cstdint>

// Problem constants
#define B_ 8
#define S_ 1024
#define E_ 1024
#define H_ 16
#define D_ 64
#define ROWS (B_ * S_)          // 8192
#define GROUPS (B_ * H_)        // 128
#define GCHUNK (S_ * D_)        // 65536 floats per (b,h) group
#define FULL 0xffffffffu

// Scratch (device globals; allocation is forbidden)
__device__ float g_q[ROWS * E_];
__device__ float g_k[ROWS * E_];
__device__ float g_v[ROWS * E_];
__device__ float g_att[ROWS * E_];

__device__ __forceinline__ uint32_t f2tf(float x) {
    uint32_t u;
    asm("cvt.rna.tf32.f32 %0, %1;" : "=r"(u) : "f"(x));
    return u;
}

__device__ __forceinline__ void mma_tf32(float c[4], uint32_t a0, uint32_t a1,
                                         uint32_t a2, uint32_t a3,
                                         uint32_t b0, uint32_t b1) {
    asm volatile(
        "mma.sync.aligned.m16n8k8.row.col.f32.tf32.tf32.f32 "
        "{%0,%1,%2,%3},{%4,%5,%6,%7},{%8,%9},{%0,%1,%2,%3};"
        : "+f"(c[0]), "+f"(c[1]), "+f"(c[2]), "+f"(c[3])
        : "r"(a0), "r"(a1), "r"(a2), "r"(a3), "r"(b0), "r"(b1));
}

// ---------------------------------------------------------------------------
// TF32 tensor-core GEMM: C[M,N] = A[M,K] @ B[K,N] (+ bias)
// BM=BN=128, BK=16, 256 threads = 8 warps (2 x 4), warp tile 64x32.
// ---------------------------------------------------------------------------
#define BM 128
#define BN 128
#define BK 16
#define SMP 132

__global__ __launch_bounds__(256) void sgemm_tf32(
    const float* __restrict__ A, const float* __restrict__ Bmat,
    const float* __restrict__ bias, float* __restrict__ C,
    int M, int N, int K)
{
    __shared__ uint32_t As[BK][SMP];
    __shared__ uint32_t Bs[BK][SMP];

    const int tid  = threadIdx.x;
    const int lane = tid & 31;
    const int wid  = tid >> 5;
    const int wm   = wid >> 2;
    const int wn   = wid & 3;
    const int gid  = lane >> 2;
    const int tig  = lane & 3;

    const int bx = blockIdx.x;
    const int by = blockIdx.y;

    const float* Ablk = A + (size_t)by * BM * K;
    const float* Bblk = Bmat + (size_t)bx * BN;

    const int ar = tid >> 1;
    const int ac = (tid & 1) * 8;
    const int br = tid >> 5;
    const int bc = (tid & 31) * 4;

    float acc[4][4][4];
    #pragma unroll
    for (int i = 0; i < 4; i++)
        #pragma unroll
        for (int j = 0; j < 4; j++)
            #pragma unroll
            for (int f = 0; f < 4; f++) acc[i][j][f] = 0.0f;

    float4 pa0, pa1, pb0, pb1;
    pa0 = *(const float4*)(Ablk + (size_t)ar * K + ac);
    pa1 = *(const float4*)(Ablk + (size_t)ar * K + ac + 4);
    pb0 = *(const float4*)(Bblk + (size_t)br * N + bc);
    pb1 = *(const float4*)(Bblk + (size_t)(br + 8) * N + bc);

    for (int k0 = 0; k0 < K; k0 += BK) {
        As[ac + 0][ar] = f2tf(pa0.x);
        As[ac + 1][ar] = f2tf(pa0.y);
        As[ac + 2][ar] = f2tf(pa0.z);
        As[ac + 3][ar] = f2tf(pa0.w);
        As[ac + 4][ar] = f2tf(pa1.x);
        As[ac + 5][ar] = f2tf(pa1.y);
        As[ac + 6][ar] = f2tf(pa1.z);
        As[ac + 7][ar] = f2tf(pa1.w);
        Bs[br][bc + 0] = f2tf(pb0.x);
        Bs[br][bc + 1] = f2tf(pb0.y);
        Bs[br][bc + 2] = f2tf(pb0.z);
        Bs[br][bc + 3] = f2tf(pb0.w);
        Bs[br + 8][bc + 0] = f2tf(pb1.x);
        Bs[br + 8][bc + 1] = f2tf(pb1.y);
        Bs[br + 8][bc + 2] = f2tf(pb1.z);
        Bs[br + 8][bc + 3] = f2tf(pb1.w);
        __syncthreads();

        if (k0 + BK < K) {
            const float* An = Ablk + k0 + BK;
            const float* Bn = Bblk + (size_t)(k0 + BK) * N;
            pa0 = *(const float4*)(An + (size_t)ar * K + ac);
            pa1 = *(const float4*)(An + (size_t)ar * K + ac + 4);
            pb0 = *(const float4*)(Bn + (size_t)br * N + bc);
            pb1 = *(const float4*)(Bn + (size_t)(br + 8) * N + bc);
        }

        #pragma unroll
        for (int s = 0; s < 2; s++) {
            const int kb = s * 8;
            uint32_t af[4][4], bf[4][2];
            #pragma unroll
            for (int i = 0; i < 4; i++) {
                const int rb = wm * 64 + i * 16;
                af[i][0] = As[kb + tig][rb + gid];
                af[i][1] = As[kb + tig][rb + 8 + gid];
                af[i][2] = As[kb + 4 + tig][rb + gid];
                af[i][3] = As[kb + 4 + tig][rb + 8 + gid];
            }
            #pragma unroll
            for (int j = 0; j < 4; j++) {
                const int cb = wn * 32 + j * 8;
                bf[j][0] = Bs[kb + tig][cb + gid];
                bf[j][1] = Bs[kb + 4 + tig][cb + gid];
            }
            #pragma unroll
            for (int i = 0; i < 4; i++)
                #pragma unroll
                for (int j = 0; j < 4; j++)
                    mma_tf32(acc[i][j], af[i][0], af[i][1], af[i][2], af[i][3],
                             bf[j][0], bf[j][1]);
        }
        __syncthreads();
    }

    #pragma unroll
    for (int i = 0; i < 4; i++) {
        const int row0 = by * BM + wm * 64 + i * 16 + gid;
        #pragma unroll
        for (int j = 0; j < 4; j++) {
            const int col = bx * BN + wn * 32 + j * 8 + 2 * tig;
            float b0 = 0.0f, b1 = 0.0f;
            if (bias != nullptr) { b0 = bias[col]; b1 = bias[col + 1]; }
            float2 v0 = make_float2(acc[i][j][0] + b0, acc[i][j][1] + b1);
            float2 v1 = make_float2(acc[i][j][2] + b0, acc[i][j][3] + b1);
            *(float2*)(C + (size_t)row0 * N + col) = v0;
            *(float2*)(C + (size_t)(row0 + 8) * N + col) = v1;
        }
    }
}

// ---------------------------------------------------------------------------
// TF32 tensor-core flash attention.
// Block = 128 threads (4 warps) = 64 query rows of one group; warp = 16 rows.
// Loop over 64-key chunks; S and P@V via m16n8k8 TF32 mma.
// grid = (S/64, GROUPS) = (16, 128)
// ---------------------------------------------------------------------------
#define KPAD 68   // K smem stride: n-major gather banks 4*gid+tig (conflict-free)
#define VPAD 72   // V smem stride: k-major gather banks 8*tig+gid (conflict-free)

__global__ __launch_bounds__(128) void attn_mma()
{
    const int g    = blockIdx.y;
    const int r0   = blockIdx.x * 64;
    const int tid  = threadIdx.x;
    const int lane = tid & 31;
    const int w    = tid >> 5;
    const int gid  = lane >> 2;
    const int tig  = lane & 3;

    const float* Qp = g_q + (size_t)g * GCHUNK;
    const float* Kp = g_k + (size_t)g * GCHUNK;
    const float* Vp = g_v + (size_t)g * GCHUNK;

    __shared__ uint32_t Ks[64][KPAD];
    __shared__ uint32_t Vs[64][VPAD];

    // ---- stage Q tile (64x64) into Ks as tf32, then gather A-fragments ----
    #pragma unroll
    for (int it = 0; it < 8; it++) {
        int slot = tid + it * 128;              // 0..1023 float4 slots
        int r  = slot >> 4;
        int c4 = (slot & 15) * 4;
        float4 v = *(const float4*)&Qp[(size_t)(r0 + r) * D_ + c4];
        Ks[r][c4 + 0] = f2tf(v.x);
        Ks[r][c4 + 1] = f2tf(v.y);
        Ks[r][c4 + 2] = f2tf(v.z);
        Ks[r][c4 + 3] = f2tf(v.w);
    }
    __syncthreads();

    uint32_t qf[8][4];
    const int qrow = w * 16;
    #pragma unroll
    for (int kd = 0; kd < 8; kd++) {
        qf[kd][0] = Ks[qrow + gid][8 * kd + tig];
        qf[kd][1] = Ks[qrow + gid + 8][8 * kd + tig];
        qf[kd][2] = Ks[qrow + gid][8 * kd + tig + 4];
        qf[kd][3] = Ks[qrow + gid + 8][8 * kd + tig + 4];
    }

    float oacc[8][4];
    #pragma unroll
    for (int jd = 0; jd < 8; jd++)
        #pragma unroll
        for (int f = 0; f < 4; f++) oacc[jd][f] = 0.0f;

    float m0 = -1e30f, m1 = -1e30f, l0 = 0.0f, l1 = 0.0f;
    const float scale = 0.03125f;              // E^-0.5

    const int srcbase = lane & ~3;
    const int src0 = srcbase | (tig >> 1);
    const int src2 = src0 + 2;
    const bool hi = tig & 1;

    for (int c0 = 0; c0 < S_; c0 += 64) {
        __syncthreads();   // Ks gather / previous chunk compute complete
        // ---- stage K and V chunks (64x64 each) ----
        #pragma unroll
        for (int it = 0; it < 8; it++) {
            int slot = tid + it * 128;
            int r  = slot >> 4;
            int c4 = (slot & 15) * 4;
            float4 kv = *(const float4*)&Kp[(size_t)(c0 + r) * D_ + c4];
            Ks[r][c4 + 0] = f2tf(kv.x);
            Ks[r][c4 + 1] = f2tf(kv.y);
            Ks[r][c4 + 2] = f2tf(kv.z);
            Ks[r][c4 + 3] = f2tf(kv.w);
            float4 vv = *(const float4*)&Vp[(size_t)(c0 + r) * D_ + c4];
            Vs[r][c4 + 0] = f2tf(vv.x);
            Vs[r][c4 + 1] = f2tf(vv.y);
            Vs[r][c4 + 2] = f2tf(vv.z);
            Vs[r][c4 + 3] = f2tf(vv.w);
        }
        __syncthreads();

        // ---- S = Q @ K^T : 8 n-tiles (keys) x 8 k-steps (d) ----
        float sacc[8][4];
        #pragma unroll
        for (int j = 0; j < 8; j++)
            #pragma unroll
            for (int f = 0; f < 4; f++) sacc[j][f] = 0.0f;

        #pragma unroll
        for (int kd = 0; kd < 8; kd++) {
            uint32_t bf[8][2];
            #pragma unroll
            for (int j = 0; j < 8; j++) {
                bf[j][0] = Ks[8 * j + gid][8 * kd + tig];
                bf[j][1] = Ks[8 * j + gid][8 * kd + tig + 4];
            }
            #pragma unroll
            for (int j = 0; j < 8; j++)
                mma_tf32(sacc[j], qf[kd][0], qf[kd][1], qf[kd][2], qf[kd][3],
                         bf[j][0], bf[j][1]);
        }

        // ---- online softmax on fragments (rows gid and gid+8) ----
        float mx0 = -1e30f, mx1 = -1e30f;
        #pragma unroll
        for (int j = 0; j < 8; j++) {
            sacc[j][0] *= scale; sacc[j][1] *= scale;
            sacc[j][2] *= scale; sacc[j][3] *= scale;
            mx0 = fmaxf(mx0, fmaxf(sacc[j][0], sacc[j][1]));
            mx1 = fmaxf(mx1, fmaxf(sacc[j][2], sacc[j][3]));
        }
        mx0 = fmaxf(mx0, __shfl_xor_sync(FULL, mx0, 1));
        mx0 = fmaxf(mx0, __shfl_xor_sync(FULL, mx0, 2));
        mx1 = fmaxf(mx1, __shfl_xor_sync(FULL, mx1, 1));
        mx1 = fmaxf(mx1, __shfl_xor_sync(FULL, mx1, 2));

        const float nm0 = fmaxf(m0, mx0);
        const float nm1 = fmaxf(m1, mx1);
        const float a0 = __expf(m0 - nm0);
        const float a1 = __expf(m1 - nm1);
        m0 = nm0; m1 = nm1;

        float rs0 = 0.0f, rs1 = 0.0f;
        #pragma unroll
        for (int j = 0; j < 8; j++) {
            sacc[j][0] = __expf(sacc[j][0] - nm0);
            sacc[j][1] = __expf(sacc[j][1] - nm0);
            sacc[j][2] = __expf(sacc[j][2] - nm1);
            sacc[j][3] = __expf(sacc[j][3] - nm1);
            rs0 += sacc[j][0] + sacc[j][1];
            rs1 += sacc[j][2] + sacc[j][3];
        }
        rs0 += __shfl_xor_sync(FULL, rs0, 1);
        rs0 += __shfl_xor_sync(FULL, rs0, 2);
        rs1 += __shfl_xor_sync(FULL, rs1, 1);
        rs1 += __shfl_xor_sync(FULL, rs1, 2);
        l0 = l0 * a0 + rs0;
        l1 = l1 * a1 + rs1;

        #pragma unroll
        for (int jd = 0; jd < 8; jd++) {
            oacc[jd][0] *= a0; oacc[jd][1] *= a0;
            oacc[jd][2] *= a1; oacc[jd][3] *= a1;
        }

        // ---- O += P @ V : relayout P (C-frag -> A-frag) via quad shuffles ----
        #pragma unroll
        for (int kk = 0; kk < 8; kk++) {
            const float p0 = sacc[kk][0], p1 = sacc[kk][1];
            const float p2 = sacc[kk][2], p3 = sacc[kk][3];
            const float x00 = __shfl_sync(FULL, p0, src0);
            const float x01 = __shfl_sync(FULL, p1, src0);
            const float x20 = __shfl_sync(FULL, p2, src0);
            const float x21 = __shfl_sync(FULL, p3, src0);
            const float y00 = __shfl_sync(FULL, p0, src2);
            const float y01 = __shfl_sync(FULL, p1, src2);
            const float y20 = __shfl_sync(FULL, p2, src2);
            const float y21 = __shfl_sync(FULL, p3, src2);
            const uint32_t af0 = f2tf(hi ? x01 : x00);
            const uint32_t af1 = f2tf(hi ? x21 : x20);
            const uint32_t af2 = f2tf(hi ? y01 : y00);
            const uint32_t af3 = f2tf(hi ? y21 : y20);
            #pragma unroll
            for (int jd = 0; jd < 8; jd++) {
                uint32_t b0 = Vs[8 * kk + tig][8 * jd + gid];
                uint32_t b1 = Vs[8 * kk + tig + 4][8 * jd + gid];
                mma_tf32(oacc[jd], af0, af1, af2, af3, b0, b1);
            }
        }
    }

    // ---- epilogue: normalize and write [B,S,H,D] ----
    const float inv0 = 1.0f / l0;
    const float inv1 = 1.0f / l1;
    const int b = g >> 4, h = g & 15;
    const int row0 = r0 + w * 16 + gid;
    #pragma unroll
    for (int jd = 0; jd < 8; jd++) {
        const int col = h * D_ + 8 * jd + 2 * tig;
        float2 v0 = make_float2(oacc[jd][0] * inv0, oacc[jd][1] * inv0);
        float2 v1 = make_float2(oacc[jd][2] * inv1, oacc[jd][3] * inv1);
        *(float2*)&g_att[(size_t)(b * S_ + row0) * E_ + col] = v0;
        *(float2*)&g_att[(size_t)(b * S_ + row0 + 8) * E_ + col] = v1;
    }
}

// ---------------------------------------------------------------------------
extern "C" void kernel_launch(void* const* d_in, const int* in_sizes, int n_in,
                              void* d_out, int out_size)
{
    const float* hs    = (const float*)d_in[0];
    const float* w_q   = (const float*)d_in[1];
    const float* w_k   = (const float*)d_in[2];
    const float* w_v   = (const float*)d_in[3];
    const float* w_out = (const float*)d_in[4];
    const float* b_out = (const float*)d_in[5];
    float* out = (float*)d_out;

    float *qp, *kp, *vp, *ap;
    cudaGetSymbolAddress((void**)&qp, g_q);
    cudaGetSymbolAddress((void**)&kp, g_k);
    cudaGetSymbolAddress((void**)&vp, g_v);
    cudaGetSymbolAddress((void**)&ap, g_att);

    dim3 gemmGrid(E_ / BN, ROWS / BM);   // (8, 64)
    sgemm_tf32<<<gemmGrid, 256>>>(hs, w_q, nullptr, qp, ROWS, E_, E_);
    sgemm_tf32<<<gemmGrid, 256>>>(hs, w_k, nullptr, kp, ROWS, E_, E_);
    sgemm_tf32<<<gemmGrid, 256>>>(hs, w_v, nullptr, vp, ROWS, E_, E_);

    dim3 attnGrid(S_ / 64, GROUPS);      // (16, 128)
    attn_mma<<<attnGrid, 128>>>();

    sgemm_tf32<<<gemmGrid, 256>>>(ap, w_out, b_out, out, ROWS, E_, E_);
}

// round 8
// speedup vs baseline: 3.3301x; 1.2951x over previous
#include <cuda_runtime.h>
#include <cuda_bf16.h>
#include <cstdint>

// Problem constants
#define B_ 8
#define S_ 1024
#define E_ 1024
#define H_ 16
#define D_ 64
#define ROWS (B_ * S_)          // 8192
#define GROUPS (B_ * H_)        // 128
#define GCHUNK (S_ * D_)        // 65536
#define FULL 0xffffffffu

// Scratch (device globals; allocation is forbidden)
__device__ float    g_q[ROWS * E_];
__device__ float    g_k[ROWS * E_];
__device__ float    g_v[ROWS * E_];
__device__ uint32_t g_attb[ROWS * E_];   // attention output, tf32 bits
__device__ uint32_t g_x[ROWS * E_];      // hidden_states, tf32 bits
__device__ uint32_t g_wt[4 * E_ * E_];   // transposed weights [N][K], tf32 bits

__device__ __forceinline__ uint32_t f2tf(float x) {
    uint32_t u;
    asm("cvt.rna.tf32.f32 %0, %1;" : "=r"(u) : "f"(x));
    return u;
}

__device__ __forceinline__ void mma_tf32(float c[4], uint32_t a0, uint32_t a1,
                                         uint32_t a2, uint32_t a3,
                                         uint32_t b0, uint32_t b1) {
    asm volatile(
        "mma.sync.aligned.m16n8k8.row.col.f32.tf32.tf32.f32 "
        "{%0,%1,%2,%3},{%4,%5,%6,%7},{%8,%9},{%0,%1,%2,%3};"
        : "+f"(c[0]), "+f"(c[1]), "+f"(c[2]), "+f"(c[3])
        : "r"(a0), "r"(a1), "r"(a2), "r"(a3), "r"(b0), "r"(b1));
}

__device__ __forceinline__ uint32_t smem_u32(const void* p) {
    uint32_t a;
    asm("{ .reg .u64 t; cvta.to.shared.u64 t, %1; cvt.u32.u64 %0, t; }"
        : "=r"(a) : "l"(p));
    return a;
}

__device__ __forceinline__ void cp16(uint32_t dst, const void* src) {
    asm volatile("cp.async.cg.shared.global [%0], [%1], 16;"
                 :: "r"(dst), "l"(src));
}
#define CPCOMMIT() asm volatile("cp.async.commit_group;" ::: "memory")
#define CPWAIT(n)  asm volatile("cp.async.wait_group %0;" :: "n"(n) : "memory")

// ===========================================================================
// Weight transpose + tf32 convert: WT[n][k] = rna_tf32(W[k][n])
// grid (32, 32, 4), block (32, 8)
// ===========================================================================
__global__ __launch_bounds__(256) void transpose_w(
    const float* __restrict__ w0, const float* __restrict__ w1,
    const float* __restrict__ w2, const float* __restrict__ w3,
    uint32_t* __restrict__ outb)
{
    __shared__ float tile[32][33];
    const float* src = (blockIdx.z == 0) ? w0 : (blockIdx.z == 1) ? w1
                     : (blockIdx.z == 2) ? w2 : w3;
    uint32_t* dst = outb + (size_t)blockIdx.z * E_ * E_;

    const int tx = threadIdx.x, ty = threadIdx.y;
    const int x = blockIdx.x * 32 + tx;       // n
    const int y = blockIdx.y * 32 + ty;       // k
    #pragma unroll
    for (int j = 0; j < 32; j += 8)
        tile[ty + j][tx] = src[(size_t)(y + j) * E_ + x];
    __syncthreads();
    const int ox = blockIdx.y * 32 + tx;      // k
    const int oy = blockIdx.x * 32 + ty;      // n
    #pragma unroll
    for (int j = 0; j < 32; j += 8)
        dst[(size_t)(oy + j) * E_ + ox] = f2tf(tile[tx][ty + j]);
}

// ===========================================================================
// Elementwise fp32 -> tf32 bits (rna) for the activation matrix.
// grid 8192, block 256, 4 elems/thread.
// ===========================================================================
__global__ __launch_bounds__(256) void convert_x(
    const float* __restrict__ in, uint32_t* __restrict__ out)
{
    const size_t i = ((size_t)blockIdx.x * 256 + threadIdx.x) * 4;
    float4 v = *(const float4*)(in + i);
    uint4 u;
    u.x = f2tf(v.x); u.y = f2tf(v.y); u.z = f2tf(v.z); u.w = f2tf(v.w);
    *(uint4*)(out + i) = u;
}

// ===========================================================================
// Pipelined TF32 mma.sync GEMM.
// A: [M][K] tf32 bits row-major. Bt: [N][K] tf32 bits row-major.
// C[m][n] = sum_k A[m][k]*Bt[n][k] (+bias).
// BM=BN=128, BK=16, 4-stage cp.async pipeline, 256 threads = 8 warps (2x4),
// warp tile 64x32. grid (E/128, ROWS/128, nmat).
// ===========================================================================
#define SK 20                    // padded smem row stride (words)
#define ASTG (128 * SK)          // words per operand per stage
#define STGW (2 * ASTG)          // words per stage
#define GSMEM (4 * STGW * 4)     // bytes: 4 stages  (81920)

__global__ __launch_bounds__(256, 2) void gemm_tc32(
    const uint32_t* __restrict__ A, const uint32_t* __restrict__ Bt_base,
    const float* __restrict__ bias,
    float* __restrict__ C0, float* __restrict__ C1, float* __restrict__ C2)
{
    extern __shared__ uint32_t sm[];
    const uint32_t sb = smem_u32(sm);

    const int tid  = threadIdx.x;
    const int lane = tid & 31;
    const int wid  = tid >> 5;
    const int wm   = wid >> 2;          // 0..1
    const int wn   = wid & 3;           // 0..3
    const int gid  = lane >> 2;         // 0..7
    const int tig  = lane & 3;          // 0..3

    const int bx = blockIdx.x, by = blockIdx.y, bz = blockIdx.z;
    const uint32_t* Bt = Bt_base + (size_t)bz * E_ * E_;
    float* C = (bz == 0) ? C0 : (bz == 1) ? C1 : C2;

    const uint32_t* Ab = A  + (size_t)by * 128 * E_;
    const uint32_t* Bb = Bt + (size_t)bx * 128 * E_;

    // loader mapping: thread -> rows lr, lr+64; 16B chunk lk
    const int lr = tid >> 2;            // 0..63
    const int lk = (tid & 3) * 4;       // 0,4,8,12

    float acc[4][4][4];
    #pragma unroll
    for (int i = 0; i < 4; i++)
        #pragma unroll
        for (int j = 0; j < 4; j++)
            #pragma unroll
            for (int f = 0; f < 4; f++) acc[i][j][f] = 0.0f;

    // ---- pipeline prologue: stages 0..2 ----
    #pragma unroll
    for (int s = 0; s < 3; s++) {
        const uint32_t ab = sb + (uint32_t)(s * STGW) * 4;
        const uint32_t bbs = ab + ASTG * 4;
        const uint32_t* ag = Ab + (size_t)lr * E_ + s * 16 + lk;
        const uint32_t* bg = Bb + (size_t)lr * E_ + s * 16 + lk;
        cp16(ab  + (uint32_t)(lr * SK + lk) * 4,        ag);
        cp16(ab  + (uint32_t)((lr + 64) * SK + lk) * 4, ag + (size_t)64 * E_);
        cp16(bbs + (uint32_t)(lr * SK + lk) * 4,        bg);
        cp16(bbs + (uint32_t)((lr + 64) * SK + lk) * 4, bg + (size_t)64 * E_);
        CPCOMMIT();
    }

    for (int c = 0; c < 64; c++) {
        CPWAIT(2);            // stage c resident (FIFO group c complete)
        __syncthreads();

        if (c + 3 < 64) {     // fill stage (c+3)&3
            const int s = (c + 3) & 3;
            const uint32_t ab = sb + (uint32_t)(s * STGW) * 4;
            const uint32_t bbs = ab + ASTG * 4;
            const uint32_t* ag = Ab + (size_t)lr * E_ + (c + 3) * 16 + lk;
            const uint32_t* bg = Bb + (size_t)lr * E_ + (c + 3) * 16 + lk;
            cp16(ab  + (uint32_t)(lr * SK + lk) * 4,        ag);
            cp16(ab  + (uint32_t)((lr + 64) * SK + lk) * 4, ag + (size_t)64 * E_);
            cp16(bbs + (uint32_t)(lr * SK + lk) * 4,        bg);
            cp16(bbs + (uint32_t)((lr + 64) * SK + lk) * 4, bg + (size_t)64 * E_);
        }
        CPCOMMIT();           // commit every iter (possibly empty) to keep FIFO uniform

        const uint32_t* As = sm + (size_t)(c & 3) * STGW;
        const uint32_t* Bs = As + ASTG;

        #pragma unroll
        for (int s8 = 0; s8 < 2; s8++) {
            const int kb = s8 * 8;
            uint32_t af[4][4], bf[4][2];
            #pragma unroll
            for (int i = 0; i < 4; i++) {
                const int rb = wm * 64 + i * 16;
                af[i][0] = As[(rb + gid) * SK + kb + tig];
                af[i][1] = As[(rb + 8 + gid) * SK + kb + tig];
                af[i][2] = As[(rb + gid) * SK + kb + tig + 4];
                af[i][3] = As[(rb + 8 + gid) * SK + kb + tig + 4];
            }
            #pragma unroll
            for (int j = 0; j < 4; j++) {
                const int cb = wn * 32 + j * 8;
                bf[j][0] = Bs[(cb + gid) * SK + kb + tig];
                bf[j][1] = Bs[(cb + gid) * SK + kb + tig + 4];
            }
            #pragma unroll
            for (int i = 0; i < 4; i++)
                #pragma unroll
                for (int j = 0; j < 4; j++)
                    mma_tf32(acc[i][j], af[i][0], af[i][1], af[i][2], af[i][3],
                             bf[j][0], bf[j][1]);
        }
    }

    // ---- epilogue ----
    #pragma unroll
    for (int i = 0; i < 4; i++) {
        const int row0 = by * 128 + wm * 64 + i * 16 + gid;
        #pragma unroll
        for (int j = 0; j < 4; j++) {
            const int col = bx * 128 + wn * 32 + j * 8 + 2 * tig;
            float b0 = 0.0f, b1 = 0.0f;
            if (bias != nullptr) { b0 = bias[col]; b1 = bias[col + 1]; }
            float2 v0 = make_float2(acc[i][j][0] + b0, acc[i][j][1] + b1);
            float2 v1 = make_float2(acc[i][j][2] + b0, acc[i][j][3] + b1);
            *(float2*)(C + (size_t)row0 * E_ + col) = v0;
            *(float2*)(C + (size_t)(row0 + 8) * E_ + col) = v1;
        }
    }
}

// ---------------------------------------------------------------------------
// TF32 tensor-core flash attention (round-4 proven). Epilogue now emits tf32
// bits straight into g_attb for the pipelined output projection.
// ---------------------------------------------------------------------------
#define KPAD 68
#define VPAD 72

__global__ __launch_bounds__(128) void attn_mma()
{
    const int g    = blockIdx.y;
    const int r0   = blockIdx.x * 64;
    const int tid  = threadIdx.x;
    const int lane = tid & 31;
    const int w    = tid >> 5;
    const int gid  = lane >> 2;
    const int tig  = lane & 3;

    const float* Qp = g_q + (size_t)g * GCHUNK;
    const float* Kp = g_k + (size_t)g * GCHUNK;
    const float* Vp = g_v + (size_t)g * GCHUNK;

    __shared__ uint32_t Ks[64][KPAD];
    __shared__ uint32_t Vs[64][VPAD];

    #pragma unroll
    for (int it = 0; it < 8; it++) {
        int slot = tid + it * 128;
        int r  = slot >> 4;
        int c4 = (slot & 15) * 4;
        float4 v = *(const float4*)&Qp[(size_t)(r0 + r) * D_ + c4];
        Ks[r][c4 + 0] = f2tf(v.x);
        Ks[r][c4 + 1] = f2tf(v.y);
        Ks[r][c4 + 2] = f2tf(v.z);
        Ks[r][c4 + 3] = f2tf(v.w);
    }
    __syncthreads();

    uint32_t qf[8][4];
    const int qrow = w * 16;
    #pragma unroll
    for (int kd = 0; kd < 8; kd++) {
        qf[kd][0] = Ks[qrow + gid][8 * kd + tig];
        qf[kd][1] = Ks[qrow + gid + 8][8 * kd + tig];
        qf[kd][2] = Ks[qrow + gid][8 * kd + tig + 4];
        qf[kd][3] = Ks[qrow + gid + 8][8 * kd + tig + 4];
    }

    float oacc[8][4];
    #pragma unroll
    for (int jd = 0; jd < 8; jd++)
        #pragma unroll
        for (int f = 0; f < 4; f++) oacc[jd][f] = 0.0f;

    float m0 = -1e30f, m1 = -1e30f, l0 = 0.0f, l1 = 0.0f;
    const float scale = 0.03125f;

    const int srcbase = lane & ~3;
    const int src0 = srcbase | (tig >> 1);
    const int src2 = src0 + 2;
    const bool hi = tig & 1;

    for (int c0 = 0; c0 < S_; c0 += 64) {
        __syncthreads();
        #pragma unroll
        for (int it = 0; it < 8; it++) {
            int slot = tid + it * 128;
            int r  = slot >> 4;
            int c4 = (slot & 15) * 4;
            float4 kv = *(const float4*)&Kp[(size_t)(c0 + r) * D_ + c4];
            Ks[r][c4 + 0] = f2tf(kv.x);
            Ks[r][c4 + 1] = f2tf(kv.y);
            Ks[r][c4 + 2] = f2tf(kv.z);
            Ks[r][c4 + 3] = f2tf(kv.w);
            float4 vv = *(const float4*)&Vp[(size_t)(c0 + r) * D_ + c4];
            Vs[r][c4 + 0] = f2tf(vv.x);
            Vs[r][c4 + 1] = f2tf(vv.y);
            Vs[r][c4 + 2] = f2tf(vv.z);
            Vs[r][c4 + 3] = f2tf(vv.w);
        }
        __syncthreads();

        float sacc[8][4];
        #pragma unroll
        for (int j = 0; j < 8; j++)
            #pragma unroll
            for (int f = 0; f < 4; f++) sacc[j][f] = 0.0f;

        #pragma unroll
        for (int kd = 0; kd < 8; kd++) {
            uint32_t bf[8][2];
            #pragma unroll
            for (int j = 0; j < 8; j++) {
                bf[j][0] = Ks[8 * j + gid][8 * kd + tig];
                bf[j][1] = Ks[8 * j + gid][8 * kd + tig + 4];
            }
            #pragma unroll
            for (int j = 0; j < 8; j++)
                mma_tf32(sacc[j], qf[kd][0], qf[kd][1], qf[kd][2], qf[kd][3],
                         bf[j][0], bf[j][1]);
        }

        float mx0 = -1e30f, mx1 = -1e30f;
        #pragma unroll
        for (int j = 0; j < 8; j++) {
            sacc[j][0] *= scale; sacc[j][1] *= scale;
            sacc[j][2] *= scale; sacc[j][3] *= scale;
            mx0 = fmaxf(mx0, fmaxf(sacc[j][0], sacc[j][1]));
            mx1 = fmaxf(mx1, fmaxf(sacc[j][2], sacc[j][3]));
        }
        mx0 = fmaxf(mx0, __shfl_xor_sync(FULL, mx0, 1));
        mx0 = fmaxf(mx0, __shfl_xor_sync(FULL, mx0, 2));
        mx1 = fmaxf(mx1, __shfl_xor_sync(FULL, mx1, 1));
        mx1 = fmaxf(mx1, __shfl_xor_sync(FULL, mx1, 2));

        const float nm0 = fmaxf(m0, mx0);
        const float nm1 = fmaxf(m1, mx1);
        const float a0 = __expf(m0 - nm0);
        const float a1 = __expf(m1 - nm1);
        m0 = nm0; m1 = nm1;

        float rs0 = 0.0f, rs1 = 0.0f;
        #pragma unroll
        for (int j = 0; j < 8; j++) {
            sacc[j][0] = __expf(sacc[j][0] - nm0);
            sacc[j][1] = __expf(sacc[j][1] - nm0);
            sacc[j][2] = __expf(sacc[j][2] - nm1);
            sacc[j][3] = __expf(sacc[j][3] - nm1);
            rs0 += sacc[j][0] + sacc[j][1];
            rs1 += sacc[j][2] + sacc[j][3];
        }
        rs0 += __shfl_xor_sync(FULL, rs0, 1);
        rs0 += __shfl_xor_sync(FULL, rs0, 2);
        rs1 += __shfl_xor_sync(FULL, rs1, 1);
        rs1 += __shfl_xor_sync(FULL, rs1, 2);
        l0 = l0 * a0 + rs0;
        l1 = l1 * a1 + rs1;

        #pragma unroll
        for (int jd = 0; jd < 8; jd++) {
            oacc[jd][0] *= a0; oacc[jd][1] *= a0;
            oacc[jd][2] *= a1; oacc[jd][3] *= a1;
        }

        #pragma unroll
        for (int kk = 0; kk < 8; kk++) {
            const float p0 = sacc[kk][0], p1 = sacc[kk][1];
            const float p2 = sacc[kk][2], p3 = sacc[kk][3];
            const float x00 = __shfl_sync(FULL, p0, src0);
            const float x01 = __shfl_sync(FULL, p1, src0);
            const float x20 = __shfl_sync(FULL, p2, src0);
            const float x21 = __shfl_sync(FULL, p3, src0);
            const float y00 = __shfl_sync(FULL, p0, src2);
            const float y01 = __shfl_sync(FULL, p1, src2);
            const float y20 = __shfl_sync(FULL, p2, src2);
            const float y21 = __shfl_sync(FULL, p3, src2);
            const uint32_t af0 = f2tf(hi ? x01 : x00);
            const uint32_t af1 = f2tf(hi ? x21 : x20);
            const uint32_t af2 = f2tf(hi ? y01 : y00);
            const uint32_t af3 = f2tf(hi ? y21 : y20);
            #pragma unroll
            for (int jd = 0; jd < 8; jd++) {
                uint32_t b0 = Vs[8 * kk + tig][8 * jd + gid];
                uint32_t b1 = Vs[8 * kk + tig + 4][8 * jd + gid];
                mma_tf32(oacc[jd], af0, af1, af2, af3, b0, b1);
            }
        }
    }

    const float inv0 = 1.0f / l0;
    const float inv1 = 1.0f / l1;
    const int b = g >> 4, h = g & 15;
    const int row0 = r0 + w * 16 + gid;
    #pragma unroll
    for (int jd = 0; jd < 8; jd++) {
        const int col = h * D_ + 8 * jd + 2 * tig;
        uint2 v0, v1;
        v0.x = f2tf(oacc[jd][0] * inv0);
        v0.y = f2tf(oacc[jd][1] * inv0);
        v1.x = f2tf(oacc[jd][2] * inv1);
        v1.y = f2tf(oacc[jd][3] * inv1);
        *(uint2*)&g_attb[(size_t)(b * S_ + row0) * E_ + col] = v0;
        *(uint2*)&g_attb[(size_t)(b * S_ + row0 + 8) * E_ + col] = v1;
    }
}

// ---------------------------------------------------------------------------
extern "C" void kernel_launch(void* const* d_in, const int* in_sizes, int n_in,
                              void* d_out, int out_size)
{
    const float* hs    = (const float*)d_in[0];
    const float* w_q   = (const float*)d_in[1];
    const float* w_k   = (const float*)d_in[2];
    const float* w_v   = (const float*)d_in[3];
    const float* w_out = (const float*)d_in[4];
    const float* b_out = (const float*)d_in[5];
    float* out = (float*)d_out;

    float *qp, *kp, *vp;
    uint32_t *wtp, *xp, *abp;
    cudaGetSymbolAddress((void**)&qp, g_q);
    cudaGetSymbolAddress((void**)&kp, g_k);
    cudaGetSymbolAddress((void**)&vp, g_v);
    cudaGetSymbolAddress((void**)&abp, g_attb);
    cudaGetSymbolAddress((void**)&xp, g_x);
    cudaGetSymbolAddress((void**)&wtp, g_wt);

    cudaFuncSetAttribute(gemm_tc32, cudaFuncAttributeMaxDynamicSharedMemorySize,
                         GSMEM);

    // 1. one-time operand conversion
    transpose_w<<<dim3(32, 32, 4), dim3(32, 8)>>>(w_q, w_k, w_v, w_out, wtp);
    convert_x<<<ROWS * E_ / 1024, 256>>>(hs, xp);

    // 2. fused QKV projections
    gemm_tc32<<<dim3(E_ / 128, ROWS / 128, 3), 256, GSMEM>>>(
        xp, wtp, nullptr, qp, kp, vp);

    // 3. attention (writes tf32 bits)
    attn_mma<<<dim3(S_ / 64, GROUPS), 128>>>();

    // 4. output projection
    gemm_tc32<<<dim3(E_ / 128, ROWS / 128, 1), 256, GSMEM>>>(
        abp, wtp + (size_t)3 * E_ * E_, b_out, out, out, out);
}

// round 11
// speedup vs baseline: 3.7620x; 1.1297x over previous
#include <cuda_runtime.h>
#include <cuda_bf16.h>
#include <cstdint>

// Problem constants
#define B_ 8
#define S_ 1024
#define E_ 1024
#define H_ 16
#define D_ 64
#define ROWS (B_ * S_)          // 8192
#define GROUPS (B_ * H_)        // 128
#define GCHUNK (S_ * D_)        // 65536
#define FULL 0xffffffffu

// Scratch (device globals; allocation is forbidden)
__device__ uint32_t g_qb[ROWS * E_];     // Q, tf32 bits
__device__ uint32_t g_kb[ROWS * E_];     // K, tf32 bits
__device__ uint32_t g_vb[ROWS * E_];     // V, tf32 bits
__device__ uint32_t g_attb[ROWS * E_];   // attention output, tf32 bits
__device__ uint32_t g_x[ROWS * E_];      // hidden_states, tf32 bits
__device__ uint32_t g_wt[4 * E_ * E_];   // transposed weights [N][K], tf32 bits

__device__ __forceinline__ uint32_t f2tf(float x) {
    uint32_t u;
    asm("cvt.rna.tf32.f32 %0, %1;" : "=r"(u) : "f"(x));
    return u;
}

__device__ __forceinline__ void mma_tf32(float c[4], uint32_t a0, uint32_t a1,
                                         uint32_t a2, uint32_t a3,
                                         uint32_t b0, uint32_t b1) {
    asm volatile(
        "mma.sync.aligned.m16n8k8.row.col.f32.tf32.tf32.f32 "
        "{%0,%1,%2,%3},{%4,%5,%6,%7},{%8,%9},{%0,%1,%2,%3};"
        : "+f"(c[0]), "+f"(c[1]), "+f"(c[2]), "+f"(c[3])
        : "r"(a0), "r"(a1), "r"(a2), "r"(a3), "r"(b0), "r"(b1));
}

__device__ __forceinline__ uint32_t smem_u32(const void* p) {
    uint32_t a;
    asm("{ .reg .u64 t; cvta.to.shared.u64 t, %1; cvt.u32.u64 %0, t; }"
        : "=r"(a) : "l"(p));
    return a;
}

__device__ __forceinline__ void cp16(uint32_t dst, const void* src) {
    asm volatile("cp.async.cg.shared.global [%0], [%1], 16;"
                 :: "r"(dst), "l"(src));
}
#define CPCOMMIT() asm volatile("cp.async.commit_group;" ::: "memory")
#define CPWAIT(n)  asm volatile("cp.async.wait_group %0;" :: "n"(n) : "memory")

// ===========================================================================
// Weight transpose + tf32 convert: WT[n][k] = rna_tf32(W[k][n])
// ===========================================================================
__global__ __launch_bounds__(256) void transpose_w(
    const float* __restrict__ w0, const float* __restrict__ w1,
    const float* __restrict__ w2, const float* __restrict__ w3,
    uint32_t* __restrict__ outb)
{
    __shared__ float tile[32][33];
    const float* src = (blockIdx.z == 0) ? w0 : (blockIdx.z == 1) ? w1
                     : (blockIdx.z == 2) ? w2 : w3;
    uint32_t* dst = outb + (size_t)blockIdx.z * E_ * E_;

    const int tx = threadIdx.x, ty = threadIdx.y;
    const int x = blockIdx.x * 32 + tx;
    const int y = blockIdx.y * 32 + ty;
    #pragma unroll
    for (int j = 0; j < 32; j += 8)
        tile[ty + j][tx] = src[(size_t)(y + j) * E_ + x];
    __syncthreads();
    const int ox = blockIdx.y * 32 + tx;
    const int oy = blockIdx.x * 32 + ty;
    #pragma unroll
    for (int j = 0; j < 32; j += 8)
        dst[(size_t)(oy + j) * E_ + ox] = f2tf(tile[tx][ty + j]);
}

// ===========================================================================
// Elementwise fp32 -> tf32 bits (rna)
// ===========================================================================
__global__ __launch_bounds__(256) void convert_x(
    const float* __restrict__ in, uint32_t* __restrict__ out)
{
    const size_t i = ((size_t)blockIdx.x * 256 + threadIdx.x) * 4;
    float4 v = *(const float4*)(in + i);
    uint4 u;
    u.x = f2tf(v.x); u.y = f2tf(v.y); u.z = f2tf(v.z); u.w = f2tf(v.w);
    *(uint4*)(out + i) = u;
}

// ===========================================================================
// Pipelined TF32 mma.sync GEMM. A:[M][K] tf32 bits, Bt:[N][K] tf32 bits.
// otf=1 -> outputs tf32 bits (for Q/K/V); otf=0 -> fp32 (+bias).
// ===========================================================================
#define SK 20
#define ASTG (128 * SK)
#define STGW (2 * ASTG)
#define GSMEM (4 * STGW * 4)

__global__ __launch_bounds__(256, 2) void gemm_tc32(
    const uint32_t* __restrict__ A, const uint32_t* __restrict__ Bt_base,
    const float* __restrict__ bias, int otf,
    float* __restrict__ C0, float* __restrict__ C1, float* __restrict__ C2)
{
    extern __shared__ uint32_t sm[];
    const uint32_t sb = smem_u32(sm);

    const int tid  = threadIdx.x;
    const int lane = tid & 31;
    const int wid  = tid >> 5;
    const int wm   = wid >> 2;
    const int wn   = wid & 3;
    const int gid  = lane >> 2;
    const int tig  = lane & 3;

    const int bx = blockIdx.x, by = blockIdx.y, bz = blockIdx.z;
    const uint32_t* Bt = Bt_base + (size_t)bz * E_ * E_;
    float* C = (bz == 0) ? C0 : (bz == 1) ? C1 : C2;

    const uint32_t* Ab = A  + (size_t)by * 128 * E_;
    const uint32_t* Bb = Bt + (size_t)bx * 128 * E_;

    const int lr = tid >> 2;
    const int lk = (tid & 3) * 4;

    float acc[4][4][4];
    #pragma unroll
    for (int i = 0; i < 4; i++)
        #pragma unroll
        for (int j = 0; j < 4; j++)
            #pragma unroll
            for (int f = 0; f < 4; f++) acc[i][j][f] = 0.0f;

    #pragma unroll
    for (int s = 0; s < 3; s++) {
        const uint32_t ab = sb + (uint32_t)(s * STGW) * 4;
        const uint32_t bbs = ab + ASTG * 4;
        const uint32_t* ag = Ab + (size_t)lr * E_ + s * 16 + lk;
        const uint32_t* bg = Bb + (size_t)lr * E_ + s * 16 + lk;
        cp16(ab  + (uint32_t)(lr * SK + lk) * 4,        ag);
        cp16(ab  + (uint32_t)((lr + 64) * SK + lk) * 4, ag + (size_t)64 * E_);
        cp16(bbs + (uint32_t)(lr * SK + lk) * 4,        bg);
        cp16(bbs + (uint32_t)((lr + 64) * SK + lk) * 4, bg + (size_t)64 * E_);
        CPCOMMIT();
    }

    for (int c = 0; c < 64; c++) {
        CPWAIT(2);
        __syncthreads();

        if (c + 3 < 64) {
            const int s = (c + 3) & 3;
            const uint32_t ab = sb + (uint32_t)(s * STGW) * 4;
            const uint32_t bbs = ab + ASTG * 4;
            const uint32_t* ag = Ab + (size_t)lr * E_ + (c + 3) * 16 + lk;
            const uint32_t* bg = Bb + (size_t)lr * E_ + (c + 3) * 16 + lk;
            cp16(ab  + (uint32_t)(lr * SK + lk) * 4,        ag);
            cp16(ab  + (uint32_t)((lr + 64) * SK + lk) * 4, ag + (size_t)64 * E_);
            cp16(bbs + (uint32_t)(lr * SK + lk) * 4,        bg);
            cp16(bbs + (uint32_t)((lr + 64) * SK + lk) * 4, bg + (size_t)64 * E_);
        }
        CPCOMMIT();

        const uint32_t* As = sm + (size_t)(c & 3) * STGW;
        const uint32_t* Bs = As + ASTG;

        #pragma unroll
        for (int s8 = 0; s8 < 2; s8++) {
            const int kb = s8 * 8;
            uint32_t af[4][4], bf[4][2];
            #pragma unroll
            for (int i = 0; i < 4; i++) {
                const int rb = wm * 64 + i * 16;
                af[i][0] = As[(rb + gid) * SK + kb + tig];
                af[i][1] = As[(rb + 8 + gid) * SK + kb + tig];
                af[i][2] = As[(rb + gid) * SK + kb + tig + 4];
                af[i][3] = As[(rb + 8 + gid) * SK + kb + tig + 4];
            }
            #pragma unroll
            for (int j = 0; j < 4; j++) {
                const int cb = wn * 32 + j * 8;
                bf[j][0] = Bs[(cb + gid) * SK + kb + tig];
                bf[j][1] = Bs[(cb + gid) * SK + kb + tig + 4];
            }
            #pragma unroll
            for (int i = 0; i < 4; i++)
                #pragma unroll
                for (int j = 0; j < 4; j++)
                    mma_tf32(acc[i][j], af[i][0], af[i][1], af[i][2], af[i][3],
                             bf[j][0], bf[j][1]);
        }
    }

    #pragma unroll
    for (int i = 0; i < 4; i++) {
        const int row0 = by * 128 + wm * 64 + i * 16 + gid;
        #pragma unroll
        for (int j = 0; j < 4; j++) {
            const int col = bx * 128 + wn * 32 + j * 8 + 2 * tig;
            float2 v0, v1;
            if (otf) {
                v0 = make_float2(__uint_as_float(f2tf(acc[i][j][0])),
                                 __uint_as_float(f2tf(acc[i][j][1])));
                v1 = make_float2(__uint_as_float(f2tf(acc[i][j][2])),
                                 __uint_as_float(f2tf(acc[i][j][3])));
            } else {
                float b0 = 0.0f, b1 = 0.0f;
                if (bias != nullptr) { b0 = bias[col]; b1 = bias[col + 1]; }
                v0 = make_float2(acc[i][j][0] + b0, acc[i][j][1] + b1);
                v1 = make_float2(acc[i][j][2] + b0, acc[i][j][3] + b1);
            }
            *(float2*)(C + (size_t)row0 * E_ + col) = v0;
            *(float2*)(C + (size_t)(row0 + 8) * E_ + col) = v1;
        }
    }
}

// ---------------------------------------------------------------------------
// TF32 tensor-core flash attention with cp.async double-buffered K/V staging.
// Block = 128 threads (4 warps) = 64 query rows; grid (S/64, GROUPS).
// Q/K/V arrive as tf32 bits (no conversion in kernel). Dynamic smem 70KB.
// ---------------------------------------------------------------------------
#define KW 68                       // K smem stride (words)
#define VW 72                       // V smem stride (words)
#define KVSTG (64 * KW + 64 * VW)   // words per stage (8960)
#define ATT_SMEM (2 * KVSTG * 4)    // 71680 bytes

__global__ __launch_bounds__(128) void attn_mma()
{
    extern __shared__ uint32_t ash[];
    const uint32_t sb = smem_u32(ash);

    const int g    = blockIdx.y;
    const int r0   = blockIdx.x * 64;
    const int tid  = threadIdx.x;
    const int lane = tid & 31;
    const int w    = tid >> 5;
    const int gid  = lane >> 2;
    const int tig  = lane & 3;

    const uint32_t* Qb = g_qb + (size_t)g * GCHUNK;
    const uint32_t* Kb = g_kb + (size_t)g * GCHUNK;
    const uint32_t* Vb = g_vb + (size_t)g * GCHUNK;

    // staging slots: 8 x 16B per operand per thread
    const int srow = tid >> 1;              // unused granularity helper
    (void)srow;

    // ---- prologue: chunk 0 K/V -> buf0 ; Q -> buf1 K-area ----
    #pragma unroll
    for (int it = 0; it < 8; it++) {
        int slot = tid + it * 128;          // 0..1023
        int r  = slot >> 4;
        int c4 = (slot & 15) * 4;
        cp16(sb + (uint32_t)(r * KW + c4) * 4,            Kb + (size_t)r * D_ + c4);
        cp16(sb + (uint32_t)(64 * KW + r * VW + c4) * 4,  Vb + (size_t)r * D_ + c4);
    }
    CPCOMMIT();
    #pragma unroll
    for (int it = 0; it < 8; it++) {
        int slot = tid + it * 128;
        int r  = slot >> 4;
        int c4 = (slot & 15) * 4;
        cp16(sb + (uint32_t)(KVSTG + r * KW + c4) * 4, Qb + (size_t)(r0 + r) * D_ + c4);
    }
    CPCOMMIT();
    CPWAIT(0);
    __syncthreads();

    // gather Q fragments from buf1 K-area
    uint32_t qf[8][4];
    {
        const uint32_t* Qs = ash + KVSTG;
        const int qrow = w * 16;
        #pragma unroll
        for (int kd = 0; kd < 8; kd++) {
            qf[kd][0] = Qs[(qrow + gid) * KW + 8 * kd + tig];
            qf[kd][1] = Qs[(qrow + gid + 8) * KW + 8 * kd + tig];
            qf[kd][2] = Qs[(qrow + gid) * KW + 8 * kd + tig + 4];
            qf[kd][3] = Qs[(qrow + gid + 8) * KW + 8 * kd + tig + 4];
        }
    }
    __syncthreads();   // all warps done with buf1 before chunk-1 loads land

    float oacc[8][4];
    #pragma unroll
    for (int jd = 0; jd < 8; jd++)
        #pragma unroll
        for (int f = 0; f < 4; f++) oacc[jd][f] = 0.0f;

    float m0 = -1e30f, m1 = -1e30f, l0 = 0.0f, l1 = 0.0f;
    const float scale = 0.03125f;

    const int srcbase = lane & ~3;
    const int src0 = srcbase | (tig >> 1);
    const int src2 = src0 + 2;
    const bool hi = tig & 1;

    for (int c = 0; c < 16; c++) {
        if (c > 0) { CPWAIT(0); __syncthreads(); }

        // issue next chunk into the other buffer (overlaps this chunk's compute)
        if (c + 1 < 16) {
            const uint32_t dstb = sb + (uint32_t)(((c + 1) & 1) * KVSTG) * 4;
            const int rbase = (c + 1) * 64;
            #pragma unroll
            for (int it = 0; it < 8; it++) {
                int slot = tid + it * 128;
                int r  = slot >> 4;
                int c4 = (slot & 15) * 4;
                cp16(dstb + (uint32_t)(r * KW + c4) * 4,
                     Kb + (size_t)(rbase + r) * D_ + c4);
                cp16(dstb + (uint32_t)(64 * KW + r * VW + c4) * 4,
                     Vb + (size_t)(rbase + r) * D_ + c4);
            }
        }
        CPCOMMIT();

        const uint32_t* Ks = ash + (size_t)(c & 1) * KVSTG;
        const uint32_t* Vs = Ks + 64 * KW;

        // ---- S = Q @ K^T ----
        float sacc[8][4];
        #pragma unroll
        for (int j = 0; j < 8; j++)
            #pragma unroll
            for (int f = 0; f < 4; f++) sacc[j][f] = 0.0f;

        #pragma unroll
        for (int kd = 0; kd < 8; kd++) {
            uint32_t bf[8][2];
            #pragma unroll
            for (int j = 0; j < 8; j++) {
                bf[j][0] = Ks[(8 * j + gid) * KW + 8 * kd + tig];
                bf[j][1] = Ks[(8 * j + gid) * KW + 8 * kd + tig + 4];
            }
            #pragma unroll
            for (int j = 0; j < 8; j++)
                mma_tf32(sacc[j], qf[kd][0], qf[kd][1], qf[kd][2], qf[kd][3],
                         bf[j][0], bf[j][1]);
        }

        // ---- online softmax ----
        float mx0 = -1e30f, mx1 = -1e30f;
        #pragma unroll
        for (int j = 0; j < 8; j++) {
            sacc[j][0] *= scale; sacc[j][1] *= scale;
            sacc[j][2] *= scale; sacc[j][3] *= scale;
            mx0 = fmaxf(mx0, fmaxf(sacc[j][0], sacc[j][1]));
            mx1 = fmaxf(mx1, fmaxf(sacc[j][2], sacc[j][3]));
        }
        mx0 = fmaxf(mx0, __shfl_xor_sync(FULL, mx0, 1));
        mx0 = fmaxf(mx0, __shfl_xor_sync(FULL, mx0, 2));
        mx1 = fmaxf(mx1, __shfl_xor_sync(FULL, mx1, 1));
        mx1 = fmaxf(mx1, __shfl_xor_sync(FULL, mx1, 2));

        const float nm0 = fmaxf(m0, mx0);
        const float nm1 = fmaxf(m1, mx1);
        const float a0 = __expf(m0 - nm0);
        const float a1 = __expf(m1 - nm1);
        m0 = nm0; m1 = nm1;

        float rs0 = 0.0f, rs1 = 0.0f;
        #pragma unroll
        for (int j = 0; j < 8; j++) {
            sacc[j][0] = __expf(sacc[j][0] - nm0);
            sacc[j][1] = __expf(sacc[j][1] - nm0);
            sacc[j][2] = __expf(sacc[j][2] - nm1);
            sacc[j][3] = __expf(sacc[j][3] - nm1);
            rs0 += sacc[j][0] + sacc[j][1];
            rs1 += sacc[j][2] + sacc[j][3];
        }
        rs0 += __shfl_xor_sync(FULL, rs0, 1);
        rs0 += __shfl_xor_sync(FULL, rs0, 2);
        rs1 += __shfl_xor_sync(FULL, rs1, 1);
        rs1 += __shfl_xor_sync(FULL, rs1, 2);
        l0 = l0 * a0 + rs0;
        l1 = l1 * a1 + rs1;

        #pragma unroll
        for (int jd = 0; jd < 8; jd++) {
            oacc[jd][0] *= a0; oacc[jd][1] *= a0;
            oacc[jd][2] *= a1; oacc[jd][3] *= a1;
        }

        // ---- O += P @ V (C-frag -> A-frag relayout via quad shuffles) ----
        #pragma unroll
        for (int kk = 0; kk < 8; kk++) {
            const float p0 = sacc[kk][0], p1 = sacc[kk][1];
            const float p2 = sacc[kk][2], p3 = sacc[kk][3];
            const float x00 = __shfl_sync(FULL, p0, src0);
            const float x01 = __shfl_sync(FULL, p1, src0);
            const float x20 = __shfl_sync(FULL, p2, src0);
            const float x21 = __shfl_sync(FULL, p3, src0);
            const float y00 = __shfl_sync(FULL, p0, src2);
            const float y01 = __shfl_sync(FULL, p1, src2);
            const float y20 = __shfl_sync(FULL, p2, src2);
            const float y21 = __shfl_sync(FULL, p3, src2);
            const uint32_t af0 = f2tf(hi ? x01 : x00);
            const uint32_t af1 = f2tf(hi ? x21 : x20);
            const uint32_t af2 = f2tf(hi ? y01 : y00);
            const uint32_t af3 = f2tf(hi ? y21 : y20);
            #pragma unroll
            for (int jd = 0; jd < 8; jd++) {
                uint32_t b0 = Vs[(8 * kk + tig) * VW + 8 * jd + gid];
                uint32_t b1 = Vs[(8 * kk + tig + 4) * VW + 8 * jd + gid];
                mma_tf32(oacc[jd], af0, af1, af2, af3, b0, b1);
            }
        }
    }

    // ---- epilogue: normalize, emit tf32 bits into [B,S,H,D] layout ----
    const float inv0 = 1.0f / l0;
    const float inv1 = 1.0f / l1;
    const int b = g >> 4, h = g & 15;
    const int row0 = r0 + w * 16 + gid;
    #pragma unroll
    for (int jd = 0; jd < 8; jd++) {
        const int col = h * D_ + 8 * jd + 2 * tig;
        uint2 v0, v1;
        v0.x = f2tf(oacc[jd][0] * inv0);
        v0.y = f2tf(oacc[jd][1] * inv0);
        v1.x = f2tf(oacc[jd][2] * inv1);
        v1.y = f2tf(oacc[jd][3] * inv1);
        *(uint2*)&g_attb[(size_t)(b * S_ + row0) * E_ + col] = v0;
        *(uint2*)&g_attb[(size_t)(b * S_ + row0 + 8) * E_ + col] = v1;
    }
}

// ---------------------------------------------------------------------------
extern "C" void kernel_launch(void* const* d_in, const int* in_sizes, int n_in,
                              void* d_out, int out_size)
{
    const float* hs    = (const float*)d_in[0];
    const float* w_q   = (const float*)d_in[1];
    const float* w_k   = (const float*)d_in[2];
    const float* w_v   = (const float*)d_in[3];
    const float* w_out = (const float*)d_in[4];
    const float* b_out = (const float*)d_in[5];
    float* out = (float*)d_out;

    uint32_t *qp, *kp, *vp, *wtp, *xp, *abp;
    cudaGetSymbolAddress((void**)&qp, g_qb);
    cudaGetSymbolAddress((void**)&kp, g_kb);
    cudaGetSymbolAddress((void**)&vp, g_vb);
    cudaGetSymbolAddress((void**)&abp, g_attb);
    cudaGetSymbolAddress((void**)&xp, g_x);
    cudaGetSymbolAddress((void**)&wtp, g_wt);

    cudaFuncSetAttribute(gemm_tc32, cudaFuncAttributeMaxDynamicSharedMemorySize,
                         GSMEM);
    cudaFuncSetAttribute(attn_mma, cudaFuncAttributeMaxDynamicSharedMemorySize,
                         ATT_SMEM);

    // 1. one-time operand conversion
    transpose_w<<<dim3(32, 32, 4), dim3(32, 8)>>>(w_q, w_k, w_v, w_out, wtp);
    convert_x<<<ROWS * E_ / 1024, 256>>>(hs, xp);

    // 2. fused QKV projections (emit tf32 bits)
    gemm_tc32<<<dim3(E_ / 128, ROWS / 128, 3), 256, GSMEM>>>(
        xp, wtp, nullptr, 1, (float*)qp, (float*)kp, (float*)vp);

    // 3. attention (tf32 in, tf32 bits out)
    attn_mma<<<dim3(S_ / 64, GROUPS), 128, ATT_SMEM>>>();

    // 4. output projection (fp32 out + bias)
    gemm_tc32<<<dim3(E_ / 128, ROWS / 128, 1), 256, GSMEM>>>(
        abp, wtp + (size_t)3 * E_ * E_, b_out, 0, out, out, out);
}